// round 14
// baseline (speedup 1.0000x reference)
#include <cuda_runtime.h>
#include <cstdint>
#include <math.h>

#define MAXN 2000000
#define MAXPART 8192

__device__ float g_e[MAXN];      // exp(beta*(1+cos)) per row
__device__ float g_w[MAXN];      // sharpened (pre-normalized) weights
__device__ float g_part1[MAXPART];
__device__ float g_part2[MAXPART];

// merge two butterfly chains at 'off': lanes with (lane&off)==0 continue chain a,
// others chain b. 2 shfls per merge.
__device__ __forceinline__ float merge2(float a, float b, int off, int lane) {
    float ta = __shfl_xor_sync(0xffffffffu, a, off);
    float tb = __shfl_xor_sync(0xffffffffu, b, off);
    return (lane & off) ? (b + tb) : (a + ta);
}

// ---------------- kernel 1: similarity + exp (the 1 GB pass) ----------------
// warp-per-row, 4 rows/tile, DEPTH-3 register pipeline (buffers rotated by
// unroll-by-3; refill issued between the FMA phase and the shfl tree so ~8
// loads stay outstanding per warp). 3 blocks/SM.
__global__ __launch_bounds__(256, 3) void k_sim(const float* __restrict__ mem,
                                                int n,
                                                const float* __restrict__ kvec,
                                                const float* __restrict__ beta_p) {
    const int lane   = threadIdx.x & 31;
    const int warp   = (blockIdx.x * blockDim.x + threadIdx.x) >> 5;
    const int nwarps = (gridDim.x * blockDim.x) >> 5;

    // inline key prep: kq = k + 1e-16, knorm = ||kq||
    float4 kv = reinterpret_cast<const float4*>(kvec)[lane];
    kv.x += 1e-16f; kv.y += 1e-16f; kv.z += 1e-16f; kv.w += 1e-16f;
    float kk = kv.x * kv.x;
    kk = fmaf(kv.y, kv.y, kk); kk = fmaf(kv.z, kv.z, kk); kk = fmaf(kv.w, kv.w, kk);
    #pragma unroll
    for (int off = 16; off; off >>= 1) kk += __shfl_xor_sync(0xffffffffu, kk, off);
    const float invknorm = 1.0f / fmaxf(sqrtf(kk), 1e-12f);
    const float beta  = *beta_p;

    // compute lanes 0,8,16,24 handle rows 0,2,1,3 after the merge-tree
    const bool is_cl  = ((lane & 7) == 0);
    const int  myrow  = ((lane >> 3) & 1) * 2 + ((lane >> 4) & 1);

    const long long stride = (long long)nwarps * 4;
    const long long nl = n;

    float acc = 0.0f;

    auto ldrow = [&](long long r) -> float4 {
        long long rr = r < nl ? r : (nl - 1);
        return __ldcs(reinterpret_cast<const float4*>(mem + rr * 128) + lane);
    };

    long long base = (long long)warp * 4;
    if (base < nl) {
        float4 A0, A1, A2, A3, B0, B1, B2, B3, C0, C1, C2, C3;

        auto ldtile = [&](long long b, float4& t0, float4& t1, float4& t2, float4& t3) {
            t0 = ldrow(b); t1 = ldrow(b + 1); t2 = ldrow(b + 2); t3 = ldrow(b + 3);
        };

        // one pipeline step: consume tile in (t0..t3) for row-base 'cur',
        // immediately refill the freed buffer with tile cur+3*stride (if valid),
        // then run the shfl tree while the refill is in flight.
        auto step = [&](float4& t0, float4& t1, float4& t2, float4& t3, long long cur) {
            float d0 = t0.x * kv.x; d0 = fmaf(t0.y, kv.y, d0); d0 = fmaf(t0.z, kv.z, d0); d0 = fmaf(t0.w, kv.w, d0);
            float d1 = t1.x * kv.x; d1 = fmaf(t1.y, kv.y, d1); d1 = fmaf(t1.z, kv.z, d1); d1 = fmaf(t1.w, kv.w, d1);
            float d2 = t2.x * kv.x; d2 = fmaf(t2.y, kv.y, d2); d2 = fmaf(t2.z, kv.z, d2); d2 = fmaf(t2.w, kv.w, d2);
            float d3 = t3.x * kv.x; d3 = fmaf(t3.y, kv.y, d3); d3 = fmaf(t3.z, kv.z, d3); d3 = fmaf(t3.w, kv.w, d3);
            float s0 = t0.x * t0.x; s0 = fmaf(t0.y, t0.y, s0); s0 = fmaf(t0.z, t0.z, s0); s0 = fmaf(t0.w, t0.w, s0);
            float s1 = t1.x * t1.x; s1 = fmaf(t1.y, t1.y, s1); s1 = fmaf(t1.z, t1.z, s1); s1 = fmaf(t1.w, t1.w, s1);
            float s2 = t2.x * t2.x; s2 = fmaf(t2.y, t2.y, s2); s2 = fmaf(t2.z, t2.z, s2); s2 = fmaf(t2.w, t2.w, s2);
            float s3 = t3.x * t3.x; s3 = fmaf(t3.y, t3.y, s3); s3 = fmaf(t3.z, t3.z, s3); s3 = fmaf(t3.w, t3.w, s3);

            // refill freed buffer (warp-uniform guard = matching compute guard)
            long long nb = cur + 3 * stride;
            if (nb < nl) ldtile(nb, t0, t1, t2, t3);

            // merge-tree reduction: 8 chains -> 1 value/lane in 16 shfls
            float m0 = merge2(d0, d1, 16, lane);
            float m1 = merge2(d2, d3, 16, lane);
            float m2 = merge2(s0, s1, 16, lane);
            float m3 = merge2(s2, s3, 16, lane);
            float n0 = merge2(m0, m1, 8, lane);
            float n1 = merge2(m2, m3, 8, lane);
            float q  = merge2(n0, n1, 4, lane);
            q += __shfl_xor_sync(0xffffffffu, q, 2);
            q += __shfl_xor_sync(0xffffffffu, q, 1);
            float qs = __shfl_xor_sync(0xffffffffu, q, 4);   // sumsq onto dot lane

            if (is_cl) {
                long long r = cur + myrow;
                if (r < nl) {
                    float cosv = q * rsqrtf(qs) * invknorm;
                    float e = __expf(fmaf(beta, cosv, beta));
                    g_e[r] = e;
                    acc += e;
                }
            }
        };

        ldtile(base, A0, A1, A2, A3);
        if (base + stride < nl)     ldtile(base + stride,     B0, B1, B2, B3);
        if (base + 2 * stride < nl) ldtile(base + 2 * stride, C0, C1, C2, C3);

        long long cur = base;
        while (true) {
            step(A0, A1, A2, A3, cur);
            cur += stride; if (cur >= nl) break;
            step(B0, B1, B2, B3, cur);
            cur += stride; if (cur >= nl) break;
            step(C0, C1, C2, C3, cur);
            cur += stride; if (cur >= nl) break;
        }
    }

    __shared__ float smr[256];
    smr[threadIdx.x] = acc;
    __syncthreads();
    for (int s = 128; s; s >>= 1) {
        if (threadIdx.x < s) smr[threadIdx.x] += smr[threadIdx.x + s];
        __syncthreads();
    }
    if (threadIdx.x == 0) g_part1[blockIdx.x] = smr[0];
}

// ---- block-wide deterministic sum of a partials array (same result in every block) ----
__device__ __forceinline__ float block_sum_partials(const float* __restrict__ part, int cnt,
                                                    float* __restrict__ sm /*256 floats*/) {
    float a = 0.f;
    for (int i = threadIdx.x; i < cnt; i += 256) a += part[i];
    sm[threadIdx.x] = a;
    __syncthreads();
    #pragma unroll
    for (int s = 128; s; s >>= 1) {
        if (threadIdx.x < s) sm[threadIdx.x] += sm[threadIdx.x + s];
        __syncthreads();
    }
    float r = sm[0];
    __syncthreads();
    return r;
}

// ---------------- kernel 2: interpolate + shift + sharpen, 4-wide ----------------
__global__ __launch_bounds__(256) void k_shift4(const float* __restrict__ wp, int n4, int n,
                                                int cnt1,
                                                const float* __restrict__ g_p,
                                                const float* __restrict__ s_p,
                                                const float* __restrict__ gamma_p) {
    __shared__ float sm[256];
    const float Se = block_sum_partials(g_part1, cnt1, sm);

    const float gg = *g_p;
    const float s0 = s_p[0], s1 = s_p[1], s2 = s_p[2];
    const float gamma = *gamma_p;
    const float one_m_g = 1.0f - gg;
    const float gs = gg / Se;

    float part = 0.f;
    int i = blockIdx.x * blockDim.x + threadIdx.x;
    if (i < n4) {
        int j = i << 2;
        int jm1 = (j == 0) ? (n - 1) : (j - 1);
        int jp4 = (j + 4 == n) ? 0 : (j + 4);

        float4 E  = reinterpret_cast<const float4*>(g_e)[i];
        float4 W  = reinterpret_cast<const float4*>(wp)[i];
        float em1 = g_e[jm1], ep4 = g_e[jp4];
        float wm1 = wp[jm1],  wp4 = wp[jp4];

        float a0 = fmaf(gs, em1, one_m_g * wm1);
        float a1 = fmaf(gs, E.x, one_m_g * W.x);
        float a2 = fmaf(gs, E.y, one_m_g * W.y);
        float a3 = fmaf(gs, E.z, one_m_g * W.z);
        float a4 = fmaf(gs, E.w, one_m_g * W.w);
        float a5 = fmaf(gs, ep4, one_m_g * wp4);

        float h0 = s0 * a0; h0 = fmaf(s1, a1, h0); h0 = fmaf(s2, a2, h0);
        float h1 = s0 * a1; h1 = fmaf(s1, a2, h1); h1 = fmaf(s2, a3, h1);
        float h2 = s0 * a2; h2 = fmaf(s1, a3, h2); h2 = fmaf(s2, a4, h2);
        float h3 = s0 * a3; h3 = fmaf(s1, a4, h3); h3 = fmaf(s2, a5, h3);

        float4 o;
        o.x = __powf(h0, gamma);
        o.y = __powf(h1, gamma);
        o.z = __powf(h2, gamma);
        o.w = __powf(h3, gamma);
        reinterpret_cast<float4*>(g_w)[i] = o;
        part = (o.x + o.y) + (o.z + o.w);
    }
    sm[threadIdx.x] = part;
    __syncthreads();
    for (int s = 128; s; s >>= 1) {
        if (threadIdx.x < s) sm[threadIdx.x] += sm[threadIdx.x + s];
        __syncthreads();
    }
    if (threadIdx.x == 0) g_part2[blockIdx.x] = sm[0];
}

// scalar fallback (n not divisible by 4)
__global__ __launch_bounds__(256) void k_shift1(const float* __restrict__ wp, int n,
                                                int cnt1,
                                                const float* __restrict__ g_p,
                                                const float* __restrict__ s_p,
                                                const float* __restrict__ gamma_p) {
    __shared__ float sm[256];
    const float Se = block_sum_partials(g_part1, cnt1, sm);

    const float gg = *g_p;
    const float s0 = s_p[0], s1 = s_p[1], s2 = s_p[2];
    const float gamma = *gamma_p;
    const float one_m_g = 1.0f - gg;
    const float gs = gg / Se;

    float part = 0.f;
    int tid = blockIdx.x * blockDim.x + threadIdx.x;
    int ntot = gridDim.x * blockDim.x;
    for (int i = tid; i < n; i += ntot) {
        int im1 = (i == 0) ? (n - 1) : (i - 1);
        int ip1 = (i == n - 1) ? 0 : (i + 1);
        float wgm = fmaf(gs, g_e[im1], one_m_g * wp[im1]);
        float wgc = fmaf(gs, g_e[i],   one_m_g * wp[i]);
        float wgp = fmaf(gs, g_e[ip1], one_m_g * wp[ip1]);
        float wh = s0 * wgm; wh = fmaf(s1, wgc, wh); wh = fmaf(s2, wgp, wh);
        float w = __powf(wh, gamma);
        g_w[i] = w;
        part += w;
    }
    sm[threadIdx.x] = part;
    __syncthreads();
    for (int s = 128; s; s >>= 1) {
        if (threadIdx.x < s) sm[threadIdx.x] += sm[threadIdx.x + s];
        __syncthreads();
    }
    if (threadIdx.x == 0) g_part2[blockIdx.x] = sm[0];
}

// ---------------- kernel 3: normalize ----------------
__global__ __launch_bounds__(256) void k_norm4(float4* __restrict__ out, int n4, int cnt2) {
    __shared__ float sm[256];
    const float Sw = block_sum_partials(g_part2, cnt2, sm);
    const float inv = 1.0f / (Sw + 1e-16f);

    int i = blockIdx.x * blockDim.x + threadIdx.x;
    if (i < n4) {
        float4 v = reinterpret_cast<const float4*>(g_w)[i];
        v.x *= inv; v.y *= inv; v.z *= inv; v.w *= inv;
        out[i] = v;
    }
}

__global__ __launch_bounds__(256) void k_norm1(float* __restrict__ out, int n, int cnt2) {
    __shared__ float sm[256];
    const float Sw = block_sum_partials(g_part2, cnt2, sm);
    const float inv = 1.0f / (Sw + 1e-16f);

    int i = blockIdx.x * blockDim.x + threadIdx.x;
    if (i < n) out[i] = g_w[i] * inv;
}

extern "C" void kernel_launch(void* const* d_in, const int* in_sizes, int n_in,
                              void* d_out, int out_size) {
    // inputs: mem [N,128], k [128], beta [1], g [1], s [3], gamma [1], w_prev [N]
    const float* mem    = (const float*)d_in[0];
    const float* k      = (const float*)d_in[1];
    const float* beta_p = (const float*)d_in[2];
    const float* g_p    = (const float*)d_in[3];
    const float* s_p    = (const float*)d_in[4];
    const float* gamma_p= (const float*)d_in[5];
    const float* wp     = (const float*)d_in[6];
    float* out = (float*)d_out;

    int n = in_sizes[6];  // N rows

    // one resident wave: 148 SMs * 3 blocks/SM = 444 blocks
    const int G1 = 444;

    k_sim<<<G1, 256>>>(mem, n, k, beta_p);

    if ((n & 3) == 0) {
        int n4 = n >> 2;
        int G3 = (n4 + 255) / 256;   // 1954 for n=2e6
        k_shift4<<<G3, 256>>>(wp, n4, n, G1, g_p, s_p, gamma_p);
        k_norm4<<<G3, 256>>>((float4*)out, n4, G3);
    } else {
        int G3 = 2048;
        k_shift1<<<G3, 256>>>(wp, n, G1, g_p, s_p, gamma_p);
        k_norm1<<<(n + 255) / 256, 256>>>(out, n, G3);
    }
}

// round 16
// speedup vs baseline: 1.1131x; 1.1131x over previous
#include <cuda_runtime.h>
#include <cstdint>
#include <math.h>

#define MAXN 2000000
#define MAXPART 8192

__device__ float g_e[MAXN];      // exp(beta*(1+cos)) per row
__device__ float g_w[MAXN];      // sharpened (pre-normalized) weights
__device__ float g_part1[MAXPART];
__device__ float g_part2[MAXPART];

// merge two butterfly chains at 'off': lanes with (lane&off)==0 continue chain a,
// others chain b. 2 shfls per merge.
__device__ __forceinline__ float merge2(float a, float b, int off, int lane) {
    float ta = __shfl_xor_sync(0xffffffffu, a, off);
    float tb = __shfl_xor_sync(0xffffffffu, b, off);
    return (lane & off) ? (b + tb) : (a + ta);
}

// ---------------- kernel 1: similarity + exp (the 1 GB pass) ----------------
// warp-per-row, 4 rows/iter, depth-2 register pipeline, merge-tree reduction.
// One resident wave (148*4 blocks), 32 warps/SM — measured local optimum.
__global__ __launch_bounds__(256) void k_sim(const float* __restrict__ mem,
                                             int n,
                                             const float* __restrict__ kvec,
                                             const float* __restrict__ beta_p) {
    const int lane   = threadIdx.x & 31;
    const int warp   = (blockIdx.x * blockDim.x + threadIdx.x) >> 5;
    const int nwarps = (gridDim.x * blockDim.x) >> 5;

    // inline key prep: kq = k + 1e-16, knorm = ||kq||
    float4 kv = reinterpret_cast<const float4*>(kvec)[lane];
    kv.x += 1e-16f; kv.y += 1e-16f; kv.z += 1e-16f; kv.w += 1e-16f;
    float kk = kv.x * kv.x;
    kk = fmaf(kv.y, kv.y, kk); kk = fmaf(kv.z, kv.z, kk); kk = fmaf(kv.w, kv.w, kk);
    #pragma unroll
    for (int off = 16; off; off >>= 1) kk += __shfl_xor_sync(0xffffffffu, kk, off);
    const float invknorm = 1.0f / fmaxf(sqrtf(kk), 1e-12f);
    const float beta  = *beta_p;

    // compute lanes 0,8,16,24 handle rows 0,2,1,3 after the merge-tree
    const bool is_cl  = ((lane & 7) == 0);
    const int  myrow  = ((lane >> 3) & 1) * 2 + ((lane >> 4) & 1);

    float acc = 0.0f;

    const long long stride = (long long)nwarps * 4;
    long long base = (long long)warp * 4;
    const long long nl = n;

    auto ldrow = [&](long long r) -> float4 {
        long long rr = r < nl ? r : (nl - 1);
        return __ldcs(reinterpret_cast<const float4*>(mem + rr * 128) + lane);
    };

    if (base < nl) {
        float4 c0 = ldrow(base);
        float4 c1 = ldrow(base + 1);
        float4 c2 = ldrow(base + 2);
        float4 c3 = ldrow(base + 3);

        while (true) {
            long long nxt = base + stride;
            float4 p0, p1, p2, p3;
            bool more = nxt < nl;
            if (more) {            // prefetch next tile (in flight during reduce)
                p0 = ldrow(nxt);
                p1 = ldrow(nxt + 1);
                p2 = ldrow(nxt + 2);
                p3 = ldrow(nxt + 3);
            }

            float d0 = c0.x * kv.x; d0 = fmaf(c0.y, kv.y, d0); d0 = fmaf(c0.z, kv.z, d0); d0 = fmaf(c0.w, kv.w, d0);
            float d1 = c1.x * kv.x; d1 = fmaf(c1.y, kv.y, d1); d1 = fmaf(c1.z, kv.z, d1); d1 = fmaf(c1.w, kv.w, d1);
            float d2 = c2.x * kv.x; d2 = fmaf(c2.y, kv.y, d2); d2 = fmaf(c2.z, kv.z, d2); d2 = fmaf(c2.w, kv.w, d2);
            float d3 = c3.x * kv.x; d3 = fmaf(c3.y, kv.y, d3); d3 = fmaf(c3.z, kv.z, d3); d3 = fmaf(c3.w, kv.w, d3);
            float s0 = c0.x * c0.x; s0 = fmaf(c0.y, c0.y, s0); s0 = fmaf(c0.z, c0.z, s0); s0 = fmaf(c0.w, c0.w, s0);
            float s1 = c1.x * c1.x; s1 = fmaf(c1.y, c1.y, s1); s1 = fmaf(c1.z, c1.z, s1); s1 = fmaf(c1.w, c1.w, s1);
            float s2 = c2.x * c2.x; s2 = fmaf(c2.y, c2.y, s2); s2 = fmaf(c2.z, c2.z, s2); s2 = fmaf(c2.w, c2.w, s2);
            float s3 = c3.x * c3.x; s3 = fmaf(c3.y, c3.y, s3); s3 = fmaf(c3.z, c3.z, s3); s3 = fmaf(c3.w, c3.w, s3);

            // merge-tree reduction: 8 chains -> 1 value/lane in 16 shfls
            float m0 = merge2(d0, d1, 16, lane);
            float m1 = merge2(d2, d3, 16, lane);
            float m2 = merge2(s0, s1, 16, lane);
            float m3 = merge2(s2, s3, 16, lane);
            float n0 = merge2(m0, m1, 8, lane);
            float n1 = merge2(m2, m3, 8, lane);
            float q  = merge2(n0, n1, 4, lane);
            q += __shfl_xor_sync(0xffffffffu, q, 2);
            q += __shfl_xor_sync(0xffffffffu, q, 1);
            float qs = __shfl_xor_sync(0xffffffffu, q, 4);   // sumsq onto dot lane

            if (is_cl) {
                long long r = base + myrow;
                if (r < nl) {
                    float cosv = q * rsqrtf(qs) * invknorm;
                    float e = __expf(fmaf(beta, cosv, beta));
                    g_e[r] = e;
                    acc += e;
                }
            }

            if (!more) break;
            base = nxt;
            c0 = p0; c1 = p1; c2 = p2; c3 = p3;
        }
    }

    __shared__ float smr[256];
    smr[threadIdx.x] = acc;
    __syncthreads();
    for (int s = 128; s; s >>= 1) {
        if (threadIdx.x < s) smr[threadIdx.x] += smr[threadIdx.x + s];
        __syncthreads();
    }
    if (threadIdx.x == 0) g_part1[blockIdx.x] = smr[0];
}

// ---- block-wide deterministic sum of a partials array (same result in every block) ----
__device__ __forceinline__ float block_sum_partials(const float* __restrict__ part, int cnt,
                                                    float* __restrict__ sm /*256 floats*/) {
    float a = 0.f;
    for (int i = threadIdx.x; i < cnt; i += 256) a += part[i];
    sm[threadIdx.x] = a;
    __syncthreads();
    #pragma unroll
    for (int s = 128; s; s >>= 1) {
        if (threadIdx.x < s) sm[threadIdx.x] += sm[threadIdx.x + s];
        __syncthreads();
    }
    float r = sm[0];
    __syncthreads();
    return r;
}

// ---------------- kernel 2: interpolate + shift + sharpen, 4-wide ----------------
__global__ __launch_bounds__(256) void k_shift4(const float* __restrict__ wp, int n4, int n,
                                                int cnt1,
                                                const float* __restrict__ g_p,
                                                const float* __restrict__ s_p,
                                                const float* __restrict__ gamma_p) {
    __shared__ float sm[256];
    const float Se = block_sum_partials(g_part1, cnt1, sm);

    const float gg = *g_p;
    const float s0 = s_p[0], s1 = s_p[1], s2 = s_p[2];
    const float gamma = *gamma_p;
    const float one_m_g = 1.0f - gg;
    const float gs = gg / Se;

    float part = 0.f;
    int i = blockIdx.x * blockDim.x + threadIdx.x;
    if (i < n4) {
        int j = i << 2;
        int jm1 = (j == 0) ? (n - 1) : (j - 1);
        int jp4 = (j + 4 == n) ? 0 : (j + 4);

        float4 E  = reinterpret_cast<const float4*>(g_e)[i];
        float4 W  = reinterpret_cast<const float4*>(wp)[i];
        float em1 = g_e[jm1], ep4 = g_e[jp4];
        float wm1 = wp[jm1],  wp4 = wp[jp4];

        float a0 = fmaf(gs, em1, one_m_g * wm1);
        float a1 = fmaf(gs, E.x, one_m_g * W.x);
        float a2 = fmaf(gs, E.y, one_m_g * W.y);
        float a3 = fmaf(gs, E.z, one_m_g * W.z);
        float a4 = fmaf(gs, E.w, one_m_g * W.w);
        float a5 = fmaf(gs, ep4, one_m_g * wp4);

        float h0 = s0 * a0; h0 = fmaf(s1, a1, h0); h0 = fmaf(s2, a2, h0);
        float h1 = s0 * a1; h1 = fmaf(s1, a2, h1); h1 = fmaf(s2, a3, h1);
        float h2 = s0 * a2; h2 = fmaf(s1, a3, h2); h2 = fmaf(s2, a4, h2);
        float h3 = s0 * a3; h3 = fmaf(s1, a4, h3); h3 = fmaf(s2, a5, h3);

        float4 o;
        o.x = __powf(h0, gamma);
        o.y = __powf(h1, gamma);
        o.z = __powf(h2, gamma);
        o.w = __powf(h3, gamma);
        reinterpret_cast<float4*>(g_w)[i] = o;
        part = (o.x + o.y) + (o.z + o.w);
    }
    sm[threadIdx.x] = part;
    __syncthreads();
    for (int s = 128; s; s >>= 1) {
        if (threadIdx.x < s) sm[threadIdx.x] += sm[threadIdx.x + s];
        __syncthreads();
    }
    if (threadIdx.x == 0) g_part2[blockIdx.x] = sm[0];
}

// scalar fallback (n not divisible by 4)
__global__ __launch_bounds__(256) void k_shift1(const float* __restrict__ wp, int n,
                                                int cnt1,
                                                const float* __restrict__ g_p,
                                                const float* __restrict__ s_p,
                                                const float* __restrict__ gamma_p) {
    __shared__ float sm[256];
    const float Se = block_sum_partials(g_part1, cnt1, sm);

    const float gg = *g_p;
    const float s0 = s_p[0], s1 = s_p[1], s2 = s_p[2];
    const float gamma = *gamma_p;
    const float one_m_g = 1.0f - gg;
    const float gs = gg / Se;

    float part = 0.f;
    int tid = blockIdx.x * blockDim.x + threadIdx.x;
    int ntot = gridDim.x * blockDim.x;
    for (int i = tid; i < n; i += ntot) {
        int im1 = (i == 0) ? (n - 1) : (i - 1);
        int ip1 = (i == n - 1) ? 0 : (i + 1);
        float wgm = fmaf(gs, g_e[im1], one_m_g * wp[im1]);
        float wgc = fmaf(gs, g_e[i],   one_m_g * wp[i]);
        float wgp = fmaf(gs, g_e[ip1], one_m_g * wp[ip1]);
        float wh = s0 * wgm; wh = fmaf(s1, wgc, wh); wh = fmaf(s2, wgp, wh);
        float w = __powf(wh, gamma);
        g_w[i] = w;
        part += w;
    }
    sm[threadIdx.x] = part;
    __syncthreads();
    for (int s = 128; s; s >>= 1) {
        if (threadIdx.x < s) sm[threadIdx.x] += sm[threadIdx.x + s];
        __syncthreads();
    }
    if (threadIdx.x == 0) g_part2[blockIdx.x] = sm[0];
}

// ---------------- kernel 3: normalize ----------------
__global__ __launch_bounds__(256) void k_norm4(float4* __restrict__ out, int n4, int cnt2) {
    __shared__ float sm[256];
    const float Sw = block_sum_partials(g_part2, cnt2, sm);
    const float inv = 1.0f / (Sw + 1e-16f);

    int i = blockIdx.x * blockDim.x + threadIdx.x;
    if (i < n4) {
        float4 v = reinterpret_cast<const float4*>(g_w)[i];
        v.x *= inv; v.y *= inv; v.z *= inv; v.w *= inv;
        out[i] = v;
    }
}

__global__ __launch_bounds__(256) void k_norm1(float* __restrict__ out, int n, int cnt2) {
    __shared__ float sm[256];
    const float Sw = block_sum_partials(g_part2, cnt2, sm);
    const float inv = 1.0f / (Sw + 1e-16f);

    int i = blockIdx.x * blockDim.x + threadIdx.x;
    if (i < n) out[i] = g_w[i] * inv;
}

extern "C" void kernel_launch(void* const* d_in, const int* in_sizes, int n_in,
                              void* d_out, int out_size) {
    // inputs: mem [N,128], k [128], beta [1], g [1], s [3], gamma [1], w_prev [N]
    const float* mem    = (const float*)d_in[0];
    const float* k      = (const float*)d_in[1];
    const float* beta_p = (const float*)d_in[2];
    const float* g_p    = (const float*)d_in[3];
    const float* s_p    = (const float*)d_in[4];
    const float* gamma_p= (const float*)d_in[5];
    const float* wp     = (const float*)d_in[6];
    float* out = (float*)d_out;

    int n = in_sizes[6];  // N rows

    // one resident wave: 148 SMs * 4 blocks/SM (64 regs, 256 thr) = 592 blocks
    const int G1 = 592;

    k_sim<<<G1, 256>>>(mem, n, k, beta_p);

    if ((n & 3) == 0) {
        int n4 = n >> 2;
        int G3 = (n4 + 255) / 256;   // 1954 for n=2e6
        k_shift4<<<G3, 256>>>(wp, n4, n, G1, g_p, s_p, gamma_p);
        k_norm4<<<G3, 256>>>((float4*)out, n4, G3);
    } else {
        int G3 = 2048;
        k_shift1<<<G3, 256>>>(wp, n, G1, g_p, s_p, gamma_p);
        k_norm1<<<(n + 255) / 256, 256>>>(out, n, G3);
    }
}

// round 17
// speedup vs baseline: 1.1409x; 1.0250x over previous
#include <cuda_runtime.h>
#include <cstdint>
#include <math.h>

#define MAXN 2000000
#define MAXPART 8192
#define GRID_BLOCKS 592   // 148 SMs * 4 blocks/SM = one guaranteed-resident wave

__device__ float g_e[MAXN];      // exp(beta*(1+cos)) per row
__device__ float g_w[MAXN];      // sharpened (pre-normalized) weights
__device__ float g_part1[MAXPART];
__device__ float g_part2[MAXPART];

// software grid barrier (sense-reversal via generation counter)
__device__ unsigned int g_barcnt;            // zero-initialized at module load
__device__ volatile unsigned int g_bargen;   // monotonically increases across replays

__device__ __forceinline__ void grid_sync() {
    __syncthreads();
    if (threadIdx.x == 0) {
        __threadfence();                         // release this block's writes
        unsigned int gen = g_bargen;
        if (atomicAdd(&g_barcnt, 1) == GRID_BLOCKS - 1) {
            g_barcnt = 0;
            __threadfence();
            g_bargen = gen + 1;
        } else {
            while (g_bargen == gen) { }
        }
        __threadfence();                         // acquire other blocks' writes
    }
    __syncthreads();
}

// merge two butterfly chains at 'off': lanes with (lane&off)==0 continue chain a,
// others chain b. 2 shfls per merge.
__device__ __forceinline__ float merge2(float a, float b, int off, int lane) {
    float ta = __shfl_xor_sync(0xffffffffu, a, off);
    float tb = __shfl_xor_sync(0xffffffffu, b, off);
    return (lane & off) ? (b + tb) : (a + ta);
}

// block-wide deterministic sum of a partials array (identical result in every block)
__device__ __forceinline__ float block_sum_partials(const float* __restrict__ part, int cnt,
                                                    float* __restrict__ sm /*256 floats*/) {
    float a = 0.f;
    for (int i = threadIdx.x; i < cnt; i += 256) a += part[i];
    sm[threadIdx.x] = a;
    __syncthreads();
    #pragma unroll
    for (int s = 128; s; s >>= 1) {
        if (threadIdx.x < s) sm[threadIdx.x] += sm[threadIdx.x + s];
        __syncthreads();
    }
    float r = sm[0];
    __syncthreads();
    return r;
}

// ---------------- single persistent fused kernel ----------------
// Phase 1: cosine-sim + exp over mem (1 GB stream)    -> g_e, block partials
// Phase 2: interpolate + circular shift + sharpen     -> g_w, block partials
// Phase 3: normalize                                  -> out
__global__ __launch_bounds__(256, 4) void k_fused(const float* __restrict__ mem,
                                                  int n,
                                                  const float* __restrict__ kvec,
                                                  const float* __restrict__ beta_p,
                                                  const float* __restrict__ g_p,
                                                  const float* __restrict__ s_p,
                                                  const float* __restrict__ gamma_p,
                                                  float* __restrict__ out) {
    __shared__ float smr[256];

    const int lane = threadIdx.x & 31;
    const int warp = (blockIdx.x * blockDim.x + threadIdx.x) >> 5;
    const int nwarps = (GRID_BLOCKS * 256) >> 5;

    // ---------- phase 1: similarity + exp ----------
    {
        // inline key prep: kq = k + 1e-16, knorm = ||kq||
        float4 kv = reinterpret_cast<const float4*>(kvec)[lane];
        kv.x += 1e-16f; kv.y += 1e-16f; kv.z += 1e-16f; kv.w += 1e-16f;
        float kk = kv.x * kv.x;
        kk = fmaf(kv.y, kv.y, kk); kk = fmaf(kv.z, kv.z, kk); kk = fmaf(kv.w, kv.w, kk);
        #pragma unroll
        for (int off = 16; off; off >>= 1) kk += __shfl_xor_sync(0xffffffffu, kk, off);
        const float invknorm = 1.0f / fmaxf(sqrtf(kk), 1e-12f);
        const float beta  = *beta_p;

        const bool is_cl  = ((lane & 7) == 0);
        const int  myrow  = ((lane >> 3) & 1) * 2 + ((lane >> 4) & 1);

        float acc = 0.0f;

        const long long stride = (long long)nwarps * 4;
        long long base = (long long)warp * 4;
        const long long nl = n;

        auto ldrow = [&](long long r) -> float4 {
            long long rr = r < nl ? r : (nl - 1);
            return __ldcs(reinterpret_cast<const float4*>(mem + rr * 128) + lane);
        };

        if (base < nl) {
            float4 c0 = ldrow(base);
            float4 c1 = ldrow(base + 1);
            float4 c2 = ldrow(base + 2);
            float4 c3 = ldrow(base + 3);

            while (true) {
                long long nxt = base + stride;
                float4 p0, p1, p2, p3;
                bool more = nxt < nl;
                if (more) {            // prefetch next tile (in flight during reduce)
                    p0 = ldrow(nxt);
                    p1 = ldrow(nxt + 1);
                    p2 = ldrow(nxt + 2);
                    p3 = ldrow(nxt + 3);
                }

                float d0 = c0.x * kv.x; d0 = fmaf(c0.y, kv.y, d0); d0 = fmaf(c0.z, kv.z, d0); d0 = fmaf(c0.w, kv.w, d0);
                float d1 = c1.x * kv.x; d1 = fmaf(c1.y, kv.y, d1); d1 = fmaf(c1.z, kv.z, d1); d1 = fmaf(c1.w, kv.w, d1);
                float d2 = c2.x * kv.x; d2 = fmaf(c2.y, kv.y, d2); d2 = fmaf(c2.z, kv.z, d2); d2 = fmaf(c2.w, kv.w, d2);
                float d3 = c3.x * kv.x; d3 = fmaf(c3.y, kv.y, d3); d3 = fmaf(c3.z, kv.z, d3); d3 = fmaf(c3.w, kv.w, d3);
                float s0 = c0.x * c0.x; s0 = fmaf(c0.y, c0.y, s0); s0 = fmaf(c0.z, c0.z, s0); s0 = fmaf(c0.w, c0.w, s0);
                float s1 = c1.x * c1.x; s1 = fmaf(c1.y, c1.y, s1); s1 = fmaf(c1.z, c1.z, s1); s1 = fmaf(c1.w, c1.w, s1);
                float s2 = c2.x * c2.x; s2 = fmaf(c2.y, c2.y, s2); s2 = fmaf(c2.z, c2.z, s2); s2 = fmaf(c2.w, c2.w, s2);
                float s3 = c3.x * c3.x; s3 = fmaf(c3.y, c3.y, s3); s3 = fmaf(c3.z, c3.z, s3); s3 = fmaf(c3.w, c3.w, s3);

                // merge-tree reduction: 8 chains -> 1 value/lane in 16 shfls
                float m0 = merge2(d0, d1, 16, lane);
                float m1 = merge2(d2, d3, 16, lane);
                float m2 = merge2(s0, s1, 16, lane);
                float m3 = merge2(s2, s3, 16, lane);
                float n0 = merge2(m0, m1, 8, lane);
                float n1 = merge2(m2, m3, 8, lane);
                float q  = merge2(n0, n1, 4, lane);
                q += __shfl_xor_sync(0xffffffffu, q, 2);
                q += __shfl_xor_sync(0xffffffffu, q, 1);
                float qs = __shfl_xor_sync(0xffffffffu, q, 4);   // sumsq onto dot lane

                if (is_cl) {
                    long long r = base + myrow;
                    if (r < nl) {
                        float cosv = q * rsqrtf(qs) * invknorm;
                        float e = __expf(fmaf(beta, cosv, beta));
                        g_e[r] = e;
                        acc += e;
                    }
                }

                if (!more) break;
                base = nxt;
                c0 = p0; c1 = p1; c2 = p2; c3 = p3;
            }
        }

        smr[threadIdx.x] = acc;
        __syncthreads();
        for (int s = 128; s; s >>= 1) {
            if (threadIdx.x < s) smr[threadIdx.x] += smr[threadIdx.x + s];
            __syncthreads();
        }
        if (threadIdx.x == 0) g_part1[blockIdx.x] = smr[0];
    }

    grid_sync();

    // ---------- phase 2: interpolate + shift + sharpen ----------
    const int tid  = blockIdx.x * 256 + threadIdx.x;
    const int ntot = GRID_BLOCKS * 256;
    {
        const float Se = block_sum_partials(g_part1, GRID_BLOCKS, smr);
        const float gg = *g_p;
        const float s0 = s_p[0], s1 = s_p[1], s2 = s_p[2];
        const float gamma = *gamma_p;
        const float one_m_g = 1.0f - gg;
        const float gs = gg / Se;
        const float* wp = out;   // placeholder; replaced below via param — see launch
        (void)wp;
    }
    // NOTE: w_prev pointer passed via s_p? No — keep explicit param list clean:
    // (w_prev passed as separate argument below)
    grid_sync();  // placeholder removed in real flow — see full body below
}

// The placeholder above is unusable; define the real fused kernel properly.
__global__ __launch_bounds__(256, 4) void k_fused_real(const float* __restrict__ mem,
                                                       int n,
                                                       const float* __restrict__ kvec,
                                                       const float* __restrict__ beta_p,
                                                       const float* __restrict__ g_p,
                                                       const float* __restrict__ s_p,
                                                       const float* __restrict__ gamma_p,
                                                       const float* __restrict__ wprev,
                                                       float* __restrict__ out) {
    __shared__ float smr[256];

    const int lane = threadIdx.x & 31;
    const int warp = (blockIdx.x * blockDim.x + threadIdx.x) >> 5;
    const int nwarps = (GRID_BLOCKS * 256) >> 5;

    // ---------- phase 1: similarity + exp ----------
    {
        float4 kv = reinterpret_cast<const float4*>(kvec)[lane];
        kv.x += 1e-16f; kv.y += 1e-16f; kv.z += 1e-16f; kv.w += 1e-16f;
        float kk = kv.x * kv.x;
        kk = fmaf(kv.y, kv.y, kk); kk = fmaf(kv.z, kv.z, kk); kk = fmaf(kv.w, kv.w, kk);
        #pragma unroll
        for (int off = 16; off; off >>= 1) kk += __shfl_xor_sync(0xffffffffu, kk, off);
        const float invknorm = 1.0f / fmaxf(sqrtf(kk), 1e-12f);
        const float beta  = *beta_p;

        const bool is_cl  = ((lane & 7) == 0);
        const int  myrow  = ((lane >> 3) & 1) * 2 + ((lane >> 4) & 1);

        float acc = 0.0f;

        const long long stride = (long long)nwarps * 4;
        long long base = (long long)warp * 4;
        const long long nl = n;

        auto ldrow = [&](long long r) -> float4 {
            long long rr = r < nl ? r : (nl - 1);
            return __ldcs(reinterpret_cast<const float4*>(mem + rr * 128) + lane);
        };

        if (base < nl) {
            float4 c0 = ldrow(base);
            float4 c1 = ldrow(base + 1);
            float4 c2 = ldrow(base + 2);
            float4 c3 = ldrow(base + 3);

            while (true) {
                long long nxt = base + stride;
                float4 p0, p1, p2, p3;
                bool more = nxt < nl;
                if (more) {
                    p0 = ldrow(nxt);
                    p1 = ldrow(nxt + 1);
                    p2 = ldrow(nxt + 2);
                    p3 = ldrow(nxt + 3);
                }

                float d0 = c0.x * kv.x; d0 = fmaf(c0.y, kv.y, d0); d0 = fmaf(c0.z, kv.z, d0); d0 = fmaf(c0.w, kv.w, d0);
                float d1 = c1.x * kv.x; d1 = fmaf(c1.y, kv.y, d1); d1 = fmaf(c1.z, kv.z, d1); d1 = fmaf(c1.w, kv.w, d1);
                float d2 = c2.x * kv.x; d2 = fmaf(c2.y, kv.y, d2); d2 = fmaf(c2.z, kv.z, d2); d2 = fmaf(c2.w, kv.w, d2);
                float d3 = c3.x * kv.x; d3 = fmaf(c3.y, kv.y, d3); d3 = fmaf(c3.z, kv.z, d3); d3 = fmaf(c3.w, kv.w, d3);
                float s0 = c0.x * c0.x; s0 = fmaf(c0.y, c0.y, s0); s0 = fmaf(c0.z, c0.z, s0); s0 = fmaf(c0.w, c0.w, s0);
                float s1 = c1.x * c1.x; s1 = fmaf(c1.y, c1.y, s1); s1 = fmaf(c1.z, c1.z, s1); s1 = fmaf(c1.w, c1.w, s1);
                float s2 = c2.x * c2.x; s2 = fmaf(c2.y, c2.y, s2); s2 = fmaf(c2.z, c2.z, s2); s2 = fmaf(c2.w, c2.w, s2);
                float s3 = c3.x * c3.x; s3 = fmaf(c3.y, c3.y, s3); s3 = fmaf(c3.z, c3.z, s3); s3 = fmaf(c3.w, c3.w, s3);

                float m0 = merge2(d0, d1, 16, lane);
                float m1 = merge2(d2, d3, 16, lane);
                float m2 = merge2(s0, s1, 16, lane);
                float m3 = merge2(s2, s3, 16, lane);
                float n0 = merge2(m0, m1, 8, lane);
                float n1 = merge2(m2, m3, 8, lane);
                float q  = merge2(n0, n1, 4, lane);
                q += __shfl_xor_sync(0xffffffffu, q, 2);
                q += __shfl_xor_sync(0xffffffffu, q, 1);
                float qs = __shfl_xor_sync(0xffffffffu, q, 4);

                if (is_cl) {
                    long long r = base + myrow;
                    if (r < nl) {
                        float cosv = q * rsqrtf(qs) * invknorm;
                        float e = __expf(fmaf(beta, cosv, beta));
                        g_e[r] = e;
                        acc += e;
                    }
                }

                if (!more) break;
                base = nxt;
                c0 = p0; c1 = p1; c2 = p2; c3 = p3;
            }
        }

        smr[threadIdx.x] = acc;
        __syncthreads();
        for (int s = 128; s; s >>= 1) {
            if (threadIdx.x < s) smr[threadIdx.x] += smr[threadIdx.x + s];
            __syncthreads();
        }
        if (threadIdx.x == 0) g_part1[blockIdx.x] = smr[0];
    }

    grid_sync();

    // ---------- phase 2: interpolate + shift + sharpen ----------
    const int tid  = blockIdx.x * 256 + threadIdx.x;
    const int ntot = GRID_BLOCKS * 256;
    {
        const float Se = block_sum_partials(g_part1, GRID_BLOCKS, smr);
        const float gg = *g_p;
        const float s0 = s_p[0], s1 = s_p[1], s2 = s_p[2];
        const float gamma = *gamma_p;
        const float one_m_g = 1.0f - gg;
        const float gs = gg / Se;

        float part = 0.f;
        if ((n & 3) == 0) {
            int n4 = n >> 2;
            for (int i = tid; i < n4; i += ntot) {
                int j = i << 2;
                int jm1 = (j == 0) ? (n - 1) : (j - 1);
                int jp4 = (j + 4 == n) ? 0 : (j + 4);

                float4 E  = reinterpret_cast<const float4*>(g_e)[i];
                float4 W  = reinterpret_cast<const float4*>(wprev)[i];
                float em1 = g_e[jm1], ep4 = g_e[jp4];
                float wm1 = wprev[jm1], wp4 = wprev[jp4];

                float a0 = fmaf(gs, em1, one_m_g * wm1);
                float a1 = fmaf(gs, E.x, one_m_g * W.x);
                float a2 = fmaf(gs, E.y, one_m_g * W.y);
                float a3 = fmaf(gs, E.z, one_m_g * W.z);
                float a4 = fmaf(gs, E.w, one_m_g * W.w);
                float a5 = fmaf(gs, ep4, one_m_g * wp4);

                float h0 = s0 * a0; h0 = fmaf(s1, a1, h0); h0 = fmaf(s2, a2, h0);
                float h1 = s0 * a1; h1 = fmaf(s1, a2, h1); h1 = fmaf(s2, a3, h1);
                float h2 = s0 * a2; h2 = fmaf(s1, a3, h2); h2 = fmaf(s2, a4, h2);
                float h3 = s0 * a3; h3 = fmaf(s1, a4, h3); h3 = fmaf(s2, a5, h3);

                float4 o;
                o.x = __powf(h0, gamma);
                o.y = __powf(h1, gamma);
                o.z = __powf(h2, gamma);
                o.w = __powf(h3, gamma);
                reinterpret_cast<float4*>(g_w)[i] = o;
                part += (o.x + o.y) + (o.z + o.w);
            }
        } else {
            for (int i = tid; i < n; i += ntot) {
                int im1 = (i == 0) ? (n - 1) : (i - 1);
                int ip1 = (i == n - 1) ? 0 : (i + 1);
                float wgm = fmaf(gs, g_e[im1], one_m_g * wprev[im1]);
                float wgc = fmaf(gs, g_e[i],   one_m_g * wprev[i]);
                float wgp = fmaf(gs, g_e[ip1], one_m_g * wprev[ip1]);
                float wh = s0 * wgm; wh = fmaf(s1, wgc, wh); wh = fmaf(s2, wgp, wh);
                float w = __powf(wh, gamma);
                g_w[i] = w;
                part += w;
            }
        }

        smr[threadIdx.x] = part;
        __syncthreads();
        for (int s = 128; s; s >>= 1) {
            if (threadIdx.x < s) smr[threadIdx.x] += smr[threadIdx.x + s];
            __syncthreads();
        }
        if (threadIdx.x == 0) g_part2[blockIdx.x] = smr[0];
    }

    grid_sync();

    // ---------- phase 3: normalize ----------
    {
        const float Sw = block_sum_partials(g_part2, GRID_BLOCKS, smr);
        const float inv = 1.0f / (Sw + 1e-16f);
        if ((n & 3) == 0) {
            int n4 = n >> 2;
            for (int i = tid; i < n4; i += ntot) {
                float4 v = reinterpret_cast<const float4*>(g_w)[i];
                v.x *= inv; v.y *= inv; v.z *= inv; v.w *= inv;
                reinterpret_cast<float4*>(out)[i] = v;
            }
        } else {
            for (int i = tid; i < n; i += ntot) out[i] = g_w[i] * inv;
        }
    }
}

extern "C" void kernel_launch(void* const* d_in, const int* in_sizes, int n_in,
                              void* d_out, int out_size) {
    // inputs: mem [N,128], k [128], beta [1], g [1], s [3], gamma [1], w_prev [N]
    const float* mem    = (const float*)d_in[0];
    const float* k      = (const float*)d_in[1];
    const float* beta_p = (const float*)d_in[2];
    const float* g_p    = (const float*)d_in[3];
    const float* s_p    = (const float*)d_in[4];
    const float* gamma_p= (const float*)d_in[5];
    const float* wp     = (const float*)d_in[6];
    float* out = (float*)d_out;

    int n = in_sizes[6];  // N rows

    k_fused_real<<<GRID_BLOCKS, 256>>>(mem, n, k, beta_p, g_p, s_p, gamma_p, wp, out);
}